// round 16
// baseline (speedup 1.0000x reference)
#include <cuda_runtime.h>
#include <cuda_bf16.h>
#include <cstdint>

// Problem constants: B=64, N=32, H=100, D=400, A=200
#define BB 64
#define NN 32
#define HH 100
#define DD 400
#define AA 200

#define XROWS 8448          // 6400 log rows + 2048 news rows
#define KP 416              // K padded to 13*32

// Scratch (allocation-free: __device__ globals)
__device__ float g_pl[BB * HH * AA];        // [b][h][a]
__device__ float g_pn[BB * NN * AA];        // [b][n][a]
__device__ float g_logits[BB * HH * NN];    // [b][h][n] masked raw logits
__device__ __nv_bfloat16 g_Xhi[XROWS * KP], g_Xlo[XROWS * KP];
__device__ __nv_bfloat16 g_Whi[2 * 256 * KP], g_Wlo[2 * 256 * KP];

// ---------------- helpers ----------------
__device__ __forceinline__ float tanh_fast(float x) {
    float y;
    asm("tanh.approx.f32 %0, %1;" : "=f"(y) : "f"(x));
    return y;
}
__device__ __forceinline__ uint32_t s2u(const void* p) {
    uint32_t a;
    asm("{ .reg .u64 t; cvta.to.shared.u64 t, %1; cvt.u32.u64 %0, t; }" : "=r"(a) : "l"(p));
    return a;
}
__device__ __forceinline__ uint32_t bpack(__nv_bfloat16 a, __nv_bfloat16 b) {
    __nv_bfloat162 t(a, b);
    return *reinterpret_cast<uint32_t*>(&t);
}
__device__ __forceinline__ void ldmx4(uint32_t* r, uint32_t addr) {
    asm volatile("ldmatrix.sync.aligned.m8n8.x4.shared.b16 {%0,%1,%2,%3}, [%4];"
                 : "=r"(r[0]), "=r"(r[1]), "=r"(r[2]), "=r"(r[3]) : "r"(addr));
}
__device__ __forceinline__ void hmma(float* d, const uint32_t* a,
                                     uint32_t b0, uint32_t b1) {
    asm("mma.sync.aligned.m16n8k16.row.col.f32.bf16.bf16.f32 "
        "{%0,%1,%2,%3}, {%4,%5,%6,%7}, {%8,%9}, {%0,%1,%2,%3};"
        : "+f"(d[0]), "+f"(d[1]), "+f"(d[2]), "+f"(d[3])
        : "r"(a[0]), "r"(a[1]), "r"(a[2]), "r"(a[3]), "r"(b0), "r"(b1));
}
#define CPA(dst, src) \
    asm volatile("cp.async.cg.shared.global [%0], [%1], 16;" \
                 :: "r"(dst), "l"(__cvta_generic_to_global(src)) : "memory")
#define CPA_COMMIT() asm volatile("cp.async.commit_group;" ::: "memory")
#define CPA_WAIT1()  asm volatile("cp.async.wait_group 1;" ::: "memory")

// ---------------- Phase 0: pre-convert f32 -> bf16 hi/lo (padded) ----------------
__device__ __forceinline__ void split4(float4 v, uint2& hi, uint2& lo) {
    __nv_bfloat16 h0 = __float2bfloat16(v.x), h1 = __float2bfloat16(v.y);
    __nv_bfloat16 h2 = __float2bfloat16(v.z), h3 = __float2bfloat16(v.w);
    __nv_bfloat16 l0 = __float2bfloat16(v.x - __bfloat162float(h0));
    __nv_bfloat16 l1 = __float2bfloat16(v.y - __bfloat162float(h1));
    __nv_bfloat16 l2 = __float2bfloat16(v.z - __bfloat162float(h2));
    __nv_bfloat16 l3 = __float2bfloat16(v.w - __bfloat162float(h3));
    hi = make_uint2(bpack(h0, h1), bpack(h2, h3));
    lo = make_uint2(bpack(l0, l1), bpack(l2, l3));
}

__global__ __launch_bounds__(256) void preconv_kernel(
    const float* __restrict__ log_vec, const float* __restrict__ news_vec,
    const float* __restrict__ W1)
{
    const int XG = XROWS * (KP / 4);          // 878592 quad-groups
    const int WG = 2 * 256 * (KP / 4);        // 53248
    int idx = blockIdx.x * 256 + threadIdx.x;
    if (idx < XG) {
        int row = idx / (KP / 4), c4 = (idx % (KP / 4)) * 4;
        float4 v = make_float4(0.f, 0.f, 0.f, 0.f);
        if (c4 < DD) {
            const float* src = (row < 6400) ? log_vec + (size_t)row * DD
                                            : news_vec + (size_t)(row - 6400) * DD;
            v = *reinterpret_cast<const float4*>(src + c4);
        }
        uint2 hi, lo;
        split4(v, hi, lo);
        *reinterpret_cast<uint2*>(g_Xhi + (size_t)row * KP + c4) = hi;
        *reinterpret_cast<uint2*>(g_Xlo + (size_t)row * KP + c4) = lo;
    } else if (idx < XG + WG) {
        int j = idx - XG;
        int half = j / (256 * (KP / 4));
        int rem = j % (256 * (KP / 4));
        int a = rem / (KP / 4), c4 = (rem % (KP / 4)) * 4;
        float4 v = make_float4(0.f, 0.f, 0.f, 0.f);
        if (a < AA && c4 < DD)
            v = *reinterpret_cast<const float4*>(W1 + (size_t)a * (2 * DD) + half * DD + c4);
        uint2 hi, lo;
        split4(v, hi, lo);
        *reinterpret_cast<uint2*>(g_Whi + (size_t)(half * 256 + a) * KP + c4) = hi;
        *reinterpret_cast<uint2*>(g_Wlo + (size_t)(half * 256 + a) * KP + c4) = lo;
    }
}

// ---------------- Phase 1: HMMA bf16 3-pass split-GEMM (cp.async pipelined) ----
#define GM 128
#define GN 64
#define NCH 13
#define ASTR 40
#define OFF_AL 10240
#define OFF_BH 20480
#define OFF_BL 25600
#define BUFB 30720
#define GSMEM (2 * BUFB)

__global__ __launch_bounds__(256) void gemm_tc_kernel(const float* __restrict__ b1)
{
    extern __shared__ __align__(16) __nv_bfloat16 smg[];
    __shared__ float b1s[GN];
    uint32_t sbase = s2u(smg);

    int tid = threadIdx.x, lane = tid & 31, wid = tid >> 5;
    int wm = wid & 3, wn = wid >> 2;

    int by = blockIdx.y;
    float* outp;
    int bm, half;
    bool bias;
    if (by < 50) { outp = g_pl; bm = by * GM;               half = 1; bias = true;  }
    else         { outp = g_pn; bm = 6400 + (by - 50) * GM; half = 0; bias = false; }
    int bn = blockIdx.x * GN;

    if (tid < GN) b1s[tid] = (bias && bn + tid < AA) ? b1[bn + tid] : 0.f;

    auto issue = [&](int c, int buf) {
        int k0 = c * 32;
        uint32_t dbase = sbase + buf * BUFB;
#pragma unroll
        for (int u = 0; u < 2; u++) {
            int id = tid + u * 256;
            int r = id >> 2, c8 = id & 3;
            uint32_t doff = (uint32_t)((r * ASTR + c8 * 8) * 2);
            size_t soff = (size_t)(bm + r) * KP + k0 + c8 * 8;
            CPA(dbase + doff, g_Xhi + soff);
            CPA(dbase + OFF_AL + doff, g_Xlo + soff);
        }
        {
            int r = tid >> 2, c8 = tid & 3;
            uint32_t doff = (uint32_t)((r * ASTR + c8 * 8) * 2);
            size_t soff = (size_t)(half * 256 + bn + r) * KP + k0 + c8 * 8;
            CPA(dbase + OFF_BH + doff, g_Whi + soff);
            CPA(dbase + OFF_BL + doff, g_Wlo + soff);
        }
    };

    float acc[8][4];
#pragma unroll
    for (int i = 0; i < 8; i++)
#pragma unroll
        for (int j = 0; j < 4; j++) acc[i][j] = 0.f;

    issue(0, 0);
    CPA_COMMIT();
    for (int c = 0; c < NCH; c++) {
        if (c + 1 < NCH) issue(c + 1, (c + 1) & 1);
        CPA_COMMIT();
        CPA_WAIT1();
        __syncthreads();

        uint32_t sAh = sbase + (c & 1) * BUFB;
        uint32_t sAl = sAh + OFF_AL, sBh = sAh + OFF_BH, sBl = sAh + OFF_BL;
#pragma unroll
        for (int ks = 0; ks < 2; ks++) {
            int kcol = ks * 16 + ((lane >> 4) << 3);
            uint32_t aoff = (uint32_t)(((wm * 32 + (lane & 15)) * ASTR + kcol) * 2);
            uint32_t boff = (uint32_t)(((wn * 32 + (lane & 15)) * ASTR + kcol) * 2);
            const uint32_t mstep = 16 * ASTR * 2;

            uint32_t ah[8], al[8], bh[8], bl[8];
            ldmx4(ah, sAh + aoff); ldmx4(ah + 4, sAh + aoff + mstep);
            ldmx4(al, sAl + aoff); ldmx4(al + 4, sAl + aoff + mstep);
            ldmx4(bh, sBh + boff); ldmx4(bh + 4, sBh + boff + mstep);
            ldmx4(bl, sBl + boff); ldmx4(bl + 4, sBl + boff + mstep);

#pragma unroll
            for (int mt = 0; mt < 2; mt++)
#pragma unroll
                for (int j = 0; j < 4; j++) {
                    int ng = j >> 1, sub = j & 1;
                    float* d = acc[mt * 4 + j];
                    hmma(d, ah + mt * 4, bh[ng * 4 + sub], bh[ng * 4 + sub + 2]);
                    hmma(d, ah + mt * 4, bl[ng * 4 + sub], bl[ng * 4 + sub + 2]);
                    hmma(d, al + mt * 4, bh[ng * 4 + sub], bh[ng * 4 + sub + 2]);
                }
        }
        __syncthreads();
    }

#pragma unroll
    for (int mt = 0; mt < 2; mt++)
#pragma unroll
        for (int j = 0; j < 4; j++) {
            int mr = bm + wm * 32 + mt * 16 + (lane >> 2);
            int ln = wn * 32 + j * 8 + 2 * (lane & 3);
            int a0 = bn + ln;
            if (a0 < AA) {
                const float* d = acc[mt * 4 + j];
                float bx = b1s[ln], by2 = b1s[ln + 1];
                int orow = (mr >= 6400) ? (mr - 6400) : mr;
                *reinterpret_cast<float2*>(outp + (size_t)orow * AA + a0) =
                    make_float2(d[0] + bx, d[1] + by2);
                *reinterpret_cast<float2*>(outp + (size_t)(orow + 8) * AA + a0) =
                    make_float2(d[2] + bx, d[3] + by2);
            }
        }
}

// ---------------- Phase 2a: logits (single wave, no reg cap) ----------------
// Block = 320 thr (10 warps); warp owns 2 h rows, lane = n. Grid 5x64 = 320
// blocks; __launch_bounds__(320,4) -> 592 slots, single wave, 51-reg budget.
// Per q-step: 1 pn LDS.128 + 1 w2 broadcast feed 8 tanh (2h x 4).
#define HT 20
#define PNP 212

__global__ __launch_bounds__(320, 4) void logits_kernel(
    const int* __restrict__ log_mask, const float* __restrict__ W2,
    const float* __restrict__ b2)
{
    __shared__ __align__(16) float pl_s[HT][AA];    // 16 KB
    __shared__ __align__(16) float pn_s[NN][PNP];   // 27.1 KB
    __shared__ __align__(16) float w2_s[AA];        // 0.8 KB

    int ht = blockIdx.x;
    int b = blockIdx.y;
    int tid = threadIdx.x;
    int lane = tid & 31;           // n
    int wid = tid >> 5;            // warp -> h pair (0..9)
    int h0 = ht * HT + wid * 2;

    const float4* plg = reinterpret_cast<const float4*>(g_pl + (b * HH + ht * HT) * AA);
    for (int i = tid; i < HT * AA / 4; i += 320) {
        int r = i / (AA / 4), c4 = i % (AA / 4);
        *reinterpret_cast<float4*>(&pl_s[r][c4 * 4]) = plg[i];
    }
    const float4* png = reinterpret_cast<const float4*>(g_pn + b * NN * AA);
    for (int i = tid; i < NN * AA / 4; i += 320) {
        int r = i / (AA / 4), c4 = i % (AA / 4);
        *reinterpret_cast<float4*>(&pn_s[r][c4 * 4]) = png[i];
    }
    for (int i = tid; i < AA / 4; i += 320)
        reinterpret_cast<float4*>(w2_s)[i] = reinterpret_cast<const float4*>(W2)[i];
    __syncthreads();

    const float4* pn4 = reinterpret_cast<const float4*>(&pn_s[lane][0]);
    const float4* pl0 = reinterpret_cast<const float4*>(&pl_s[wid * 2][0]);
    const float4* pl1 = reinterpret_cast<const float4*>(&pl_s[wid * 2 + 1][0]);
    const float4* w24 = reinterpret_cast<const float4*>(w2_s);

    float a00 = 0.f, a01 = 0.f, a10 = 0.f, a11 = 0.f;
#pragma unroll 5
    for (int q = 0; q < AA / 4; q++) {
        float4 nv = pn4[q];        // conflict-free LDS.128 (stride 212)
        float4 w = w24[q];         // broadcast
        float4 p0 = pl0[q];        // broadcast
        float4 p1 = pl1[q];        // broadcast
        a00 = fmaf(tanh_fast(p0.x + nv.x), w.x, a00);
        a01 = fmaf(tanh_fast(p0.y + nv.y), w.y, a01);
        a10 = fmaf(tanh_fast(p1.x + nv.x), w.x, a10);
        a11 = fmaf(tanh_fast(p1.y + nv.y), w.y, a11);
        a00 = fmaf(tanh_fast(p0.z + nv.z), w.z, a00);
        a01 = fmaf(tanh_fast(p0.w + nv.w), w.w, a01);
        a10 = fmaf(tanh_fast(p1.z + nv.z), w.z, a10);
        a11 = fmaf(tanh_fast(p1.w + nv.w), w.w, a11);
    }

    float b2v = b2[0];
    float v0 = (log_mask[b * HH + h0] == 0) ? -1e9f : (a00 + a01 + b2v);
    float v1 = (log_mask[b * HH + h0 + 1] == 0) ? -1e9f : (a10 + a11 + b2v);
    g_logits[(b * HH + h0) * NN + lane] = v0;       // coalesced 128B per warp
    g_logits[(b * HH + h0 + 1) * NN + lane] = v1;
}

// ---------------- Phase 2b: softmax + attention output (4n, 8192 warps) ------
__global__ __launch_bounds__(512) void out_kernel(
    const float* __restrict__ log_vec, float* __restrict__ out)
{
    __shared__ __align__(16) float at_s[HH][4];

    int ng = blockIdx.x;           // 0..7
    int b = blockIdx.y;
    int tid = threadIdx.x;
    int lane = tid & 31, warp = tid >> 5;

    const float* lg = g_logits + b * HH * NN + ng * 4;
    if (tid < HH * 4) {
        int h = tid >> 2, j = tid & 3;
        at_s[h][j] = lg[h * NN + j];
    }
    __syncthreads();

    if (warp < 4) {
        float m = -3e38f;
        for (int h = lane; h < HH; h += 32) m = fmaxf(m, at_s[h][warp]);
#pragma unroll
        for (int o = 16; o; o >>= 1) m = fmaxf(m, __shfl_xor_sync(0xffffffffu, m, o));
        float s = 0.f;
        for (int h = lane; h < HH; h += 32) {
            float e = __expf(at_s[h][warp] - m);
            at_s[h][warp] = e;
            s += e;
        }
#pragma unroll
        for (int o = 16; o; o >>= 1) s += __shfl_xor_sync(0xffffffffu, s, o);
        float r = 1.f / s;
        for (int h = lane; h < HH; h += 32) at_s[h][warp] *= r;
    }
    __syncthreads();

    if (tid < DD) {
        const float* lvd = log_vec + (size_t)b * HH * DD + tid;
        float o0 = 0.f, o1 = 0.f, o2 = 0.f, o3 = 0.f;
#pragma unroll 4
        for (int h = 0; h < HH; h += 2) {
            float v0 = lvd[h * DD];
            float v1 = lvd[(h + 1) * DD];
            float4 w0 = *reinterpret_cast<float4*>(&at_s[h][0]);
            float4 w1 = *reinterpret_cast<float4*>(&at_s[h + 1][0]);
            o0 = fmaf(w0.x, v0, o0);
            o1 = fmaf(w0.y, v0, o1);
            o2 = fmaf(w0.z, v0, o2);
            o3 = fmaf(w0.w, v0, o3);
            o0 = fmaf(w1.x, v1, o0);
            o1 = fmaf(w1.y, v1, o1);
            o2 = fmaf(w1.z, v1, o2);
            o3 = fmaf(w1.w, v1, o3);
        }
        int nbase = b * NN + ng * 4;
        out[(size_t)(nbase + 0) * DD + tid] = o0;
        out[(size_t)(nbase + 1) * DD + tid] = o1;
        out[(size_t)(nbase + 2) * DD + tid] = o2;
        out[(size_t)(nbase + 3) * DD + tid] = o3;
    }
}

// ---------------- launch ----------------
extern "C" void kernel_launch(void* const* d_in, const int* in_sizes, int n_in,
                              void* d_out, int out_size) {
    const float* log_vec  = (const float*)d_in[0];   // [64,100,400] f32
    const int*   log_mask = (const int*)d_in[1];     // [64,100] i32
    const float* news_vec = (const float*)d_in[2];   // [64,32,400] f32
    const float* W1       = (const float*)d_in[3];   // [200,800] f32
    const float* b1       = (const float*)d_in[4];   // [200] f32
    const float* W2       = (const float*)d_in[5];   // [1,200] f32
    const float* b2       = (const float*)d_in[6];   // [1] f32
    float* out = (float*)d_out;                      // [64,32,400] f32

    const int XG = XROWS * (KP / 4), WG = 2 * 256 * (KP / 4);
    preconv_kernel<<<(XG + WG + 255) / 256, 256>>>(log_vec, news_vec, W1);

    cudaFuncSetAttribute(gemm_tc_kernel, cudaFuncAttributeMaxDynamicSharedMemorySize, GSMEM);
    gemm_tc_kernel<<<dim3(4, 66), 256, GSMEM>>>(b1);

    logits_kernel<<<dim3(HH / HT, BB), 320>>>(log_mask, W2, b2);
    out_kernel<<<dim3(NN / 4, BB), 512>>>(log_vec, out);
}

// round 17
// speedup vs baseline: 1.1132x; 1.1132x over previous
#include <cuda_runtime.h>
#include <cuda_bf16.h>
#include <cstdint>

// Problem constants: B=64, N=32, H=100, D=400, A=200
#define BB 64
#define NN 32
#define HH 100
#define DD 400
#define AA 200

// Scratch (allocation-free: __device__ globals)
__device__ float g_pl[BB * HH * AA];        // [b][h][a]
__device__ float g_pn[BB * NN * AA];        // [b][n][a]
__device__ float g_logits[BB * HH * NN];    // [b][h][n] masked raw logits

// ---------------- helpers ----------------
__device__ __forceinline__ float tanh_fast(float x) {
    float y;
    asm("tanh.approx.f32 %0, %1;" : "=f"(y) : "f"(x));
    return y;
}
__device__ __forceinline__ uint32_t s2u(const void* p) {
    uint32_t a;
    asm("{ .reg .u64 t; cvta.to.shared.u64 t, %1; cvt.u32.u64 %0, t; }" : "=r"(a) : "l"(p));
    return a;
}
__device__ __forceinline__ uint32_t bpack(__nv_bfloat16 a, __nv_bfloat16 b) {
    __nv_bfloat162 t(a, b);
    return *reinterpret_cast<uint32_t*>(&t);
}
__device__ __forceinline__ void ldmx4(uint32_t* r, uint32_t addr) {
    asm volatile("ldmatrix.sync.aligned.m8n8.x4.shared.b16 {%0,%1,%2,%3}, [%4];"
                 : "=r"(r[0]), "=r"(r[1]), "=r"(r[2]), "=r"(r[3]) : "r"(addr));
}
__device__ __forceinline__ void hmma(float* d, const uint32_t* a,
                                     uint32_t b0, uint32_t b1) {
    asm("mma.sync.aligned.m16n8k16.row.col.f32.bf16.bf16.f32 "
        "{%0,%1,%2,%3}, {%4,%5,%6,%7}, {%8,%9}, {%0,%1,%2,%3};"
        : "+f"(d[0]), "+f"(d[1]), "+f"(d[2]), "+f"(d[3])
        : "r"(a[0]), "r"(a[1]), "r"(a[2]), "r"(a[3]), "r"(b0), "r"(b1));
}

// ---------------- Phase 1: HMMA bf16 3-pass split-GEMM (R10 monolithic) ----
// out[m][a] = sum_k X[m][k] * W1[a][koff+k]   (f32 via Ah*Bh + Ah*Bl + Al*Bh)
// CTA 128m x 64a, 256 thr = 8 warps (4m x 2n), warp 32x32, K-chunks of 32.
#define GM 128
#define GN 64
#define KC 32
#define NCH 13            // 13*32 = 416 >= 400 (zero-padded)
#define ASTR 40           // smem row stride in bf16 (80B: ldmatrix conflict-free)

__global__ __launch_bounds__(256) void gemm_tc_kernel(
    const float* __restrict__ log_vec, const float* __restrict__ news_vec,
    const float* __restrict__ W1, const float* __restrict__ b1)
{
    __shared__ __align__(16) __nv_bfloat16 Ah[GM * ASTR], Al[GM * ASTR];
    __shared__ __align__(16) __nv_bfloat16 Bh[GN * ASTR], Bl[GN * ASTR];
    __shared__ float b1s[GN];

    int tid = threadIdx.x, lane = tid & 31, wid = tid >> 5;
    int wm = wid & 3;          // m-group (32 rows)
    int wn = wid >> 2;         // n-group (32 cols)

    int by = blockIdx.y;
    const float* X;
    float* outp;
    int koff, bm;
    bool bias;
    if (by < 50) { X = log_vec;  outp = g_pl; koff = DD; bm = by * GM;        bias = true;  }
    else         { X = news_vec; outp = g_pn; koff = 0;  bm = (by - 50) * GM; bias = false; }
    int bn = blockIdx.x * GN;

    if (tid < GN) b1s[tid] = (bias && bn + tid < AA) ? b1[bn + tid] : 0.f;

    uint32_t sAh = s2u(Ah), sAl = s2u(Al), sBh = s2u(Bh), sBl = s2u(Bl);

    // ldg staging regs
    float4 xa[4], xb[2];
    auto ldgA = [&](int c) {
        int k0 = c * KC;
#pragma unroll
        for (int u = 0; u < 4; u++) {
            int idx = tid + u * 256;           // 0..1023
            int r = idx >> 3, c4 = (idx & 7) << 2;
            int k = k0 + c4;
            xa[u] = (k < DD)
                ? *reinterpret_cast<const float4*>(X + (size_t)(bm + r) * DD + k)
                : make_float4(0.f, 0.f, 0.f, 0.f);
        }
    };
    auto ldgB = [&](int c) {
        int k0 = c * KC;
#pragma unroll
        for (int u = 0; u < 2; u++) {
            int idx = tid + u * 256;           // 0..511
            int r = idx >> 3, c4 = (idx & 7) << 2;
            int k = k0 + c4, a = bn + r;
            xb[u] = (a < AA && k < DD)
                ? *reinterpret_cast<const float4*>(W1 + (size_t)a * (2 * DD) + koff + k)
                : make_float4(0.f, 0.f, 0.f, 0.f);
        }
    };
    auto cvt_sts = [&](__nv_bfloat16* hi, __nv_bfloat16* lo, int r, int c4, float4 v) {
        __nv_bfloat16 h0 = __float2bfloat16(v.x), h1 = __float2bfloat16(v.y);
        __nv_bfloat16 h2 = __float2bfloat16(v.z), h3 = __float2bfloat16(v.w);
        __nv_bfloat16 l0 = __float2bfloat16(v.x - __bfloat162float(h0));
        __nv_bfloat16 l1 = __float2bfloat16(v.y - __bfloat162float(h1));
        __nv_bfloat16 l2 = __float2bfloat16(v.z - __bfloat162float(h2));
        __nv_bfloat16 l3 = __float2bfloat16(v.w - __bfloat162float(h3));
        *reinterpret_cast<uint2*>(hi + r * ASTR + c4) = make_uint2(bpack(h0, h1), bpack(h2, h3));
        *reinterpret_cast<uint2*>(lo + r * ASTR + c4) = make_uint2(bpack(l0, l1), bpack(l2, l3));
    };

    float acc[8][4];           // [mt*4 + ntile][4]
#pragma unroll
    for (int i = 0; i < 8; i++)
#pragma unroll
        for (int j = 0; j < 4; j++) acc[i][j] = 0.f;

    ldgA(0); ldgB(0);
    for (int c = 0; c < NCH; c++) {
        __syncthreads();
#pragma unroll
        for (int u = 0; u < 4; u++) {
            int idx = tid + u * 256;
            cvt_sts(Ah, Al, idx >> 3, (idx & 7) << 2, xa[u]);
        }
#pragma unroll
        for (int u = 0; u < 2; u++) {
            int idx = tid + u * 256;
            cvt_sts(Bh, Bl, idx >> 3, (idx & 7) << 2, xb[u]);
        }
        __syncthreads();
        if (c + 1 < NCH) { ldgA(c + 1); ldgB(c + 1); }

#pragma unroll
        for (int ks = 0; ks < 2; ks++) {
            int kcol = ks * 16 + ((lane >> 4) << 3);
            uint32_t aoff = (uint32_t)(((wm * 32 + (lane & 15)) * ASTR + kcol) * 2);
            uint32_t boff = (uint32_t)(((wn * 32 + (lane & 15)) * ASTR + kcol) * 2);
            const uint32_t mstep = 16 * ASTR * 2;

            uint32_t ah[8], al[8], bh[8], bl[8];
            ldmx4(ah, sAh + aoff); ldmx4(ah + 4, sAh + aoff + mstep);
            ldmx4(al, sAl + aoff); ldmx4(al + 4, sAl + aoff + mstep);
            ldmx4(bh, sBh + boff); ldmx4(bh + 4, sBh + boff + mstep);
            ldmx4(bl, sBl + boff); ldmx4(bl + 4, sBl + boff + mstep);

#pragma unroll
            for (int mt = 0; mt < 2; mt++)
#pragma unroll
                for (int j = 0; j < 4; j++) {
                    int ng = j >> 1, sub = j & 1;
                    float* d = acc[mt * 4 + j];
                    hmma(d, ah + mt * 4, bh[ng * 4 + sub], bh[ng * 4 + sub + 2]); // hi*hi
                    hmma(d, ah + mt * 4, bl[ng * 4 + sub], bl[ng * 4 + sub + 2]); // hi*lo
                    hmma(d, al + mt * 4, bh[ng * 4 + sub], bh[ng * 4 + sub + 2]); // lo*hi
                }
        }
    }

    // epilogue: direct float2 stores (+bias; b1s zeroed for pn)
#pragma unroll
    for (int mt = 0; mt < 2; mt++)
#pragma unroll
        for (int j = 0; j < 4; j++) {
            int m0 = bm + wm * 32 + mt * 16 + (lane >> 2);
            int ln = wn * 32 + j * 8 + 2 * (lane & 3);
            int a0 = bn + ln;
            if (a0 < AA) {
                const float* d = acc[mt * 4 + j];
                float bx = b1s[ln], by2 = b1s[ln + 1];
                *reinterpret_cast<float2*>(outp + (size_t)m0 * AA + a0) =
                    make_float2(d[0] + bx, d[1] + by2);
                *reinterpret_cast<float2*>(outp + (size_t)(m0 + 8) * AA + a0) =
                    make_float2(d[2] + bx, d[3] + by2);
            }
        }
}

// ---------------- Phase 2a: logits (R10 version: 640 thr, no reg cap) --------
#define HT 20
#define PNP 212

__global__ __launch_bounds__(640, 2) void logits_kernel(
    const int* __restrict__ log_mask, const float* __restrict__ W2,
    const float* __restrict__ b2)
{
    __shared__ __align__(16) float pl_s[HT][AA];
    __shared__ __align__(16) float pn_s[NN][PNP];
    __shared__ __align__(16) float w2_s[AA];

    int ht = blockIdx.x;
    int b = blockIdx.y;
    int tid = threadIdx.x;
    int lane = tid & 31;           // n
    int wid = tid >> 5;            // h within tile
    int h = ht * HT + wid;

    const float4* plg = reinterpret_cast<const float4*>(g_pl + (b * HH + ht * HT) * AA);
    for (int i = tid; i < HT * AA / 4; i += 640) {
        int r = i / (AA / 4), c4 = i % (AA / 4);
        *reinterpret_cast<float4*>(&pl_s[r][c4 * 4]) = plg[i];
    }
    const float4* png = reinterpret_cast<const float4*>(g_pn + b * NN * AA);
    for (int i = tid; i < NN * AA / 4; i += 640) {
        int r = i / (AA / 4), c4 = i % (AA / 4);
        *reinterpret_cast<float4*>(&pn_s[r][c4 * 4]) = png[i];
    }
    for (int i = tid; i < AA / 4; i += 640)
        reinterpret_cast<float4*>(w2_s)[i] = reinterpret_cast<const float4*>(W2)[i];
    __syncthreads();

    const float4* pn4 = reinterpret_cast<const float4*>(&pn_s[lane][0]);
    const float4* pl4 = reinterpret_cast<const float4*>(&pl_s[wid][0]);
    const float4* w24 = reinterpret_cast<const float4*>(w2_s);

    float acc0 = 0.f, acc1 = 0.f;
#pragma unroll 5
    for (int q = 0; q < AA / 4; q++) {
        float4 p = pl4[q];         // broadcast
        float4 nv = pn4[q];        // conflict-free LDS.128 (stride 212)
        float4 w = w24[q];         // broadcast
        acc0 = fmaf(tanh_fast(p.x + nv.x), w.x, acc0);
        acc1 = fmaf(tanh_fast(p.y + nv.y), w.y, acc1);
        acc0 = fmaf(tanh_fast(p.z + nv.z), w.z, acc0);
        acc1 = fmaf(tanh_fast(p.w + nv.w), w.w, acc1);
    }

    bool masked = (log_mask[b * HH + h] == 0);
    float v = masked ? -1e9f : (acc0 + acc1 + b2[0]);
    g_logits[(b * HH + h) * NN + lane] = v;
}

// ---------------- Phase 2b: softmax + attention output (4n, 8192 warps) ------
__global__ __launch_bounds__(512) void out_kernel(
    const float* __restrict__ log_vec, float* __restrict__ out)
{
    __shared__ __align__(16) float at_s[HH][4];

    int ng = blockIdx.x;           // 0..7
    int b = blockIdx.y;
    int tid = threadIdx.x;
    int lane = tid & 31, warp = tid >> 5;

    const float* lg = g_logits + b * HH * NN + ng * 4;
    if (tid < HH * 4) {
        int h = tid >> 2, j = tid & 3;
        at_s[h][j] = lg[h * NN + j];
    }
    __syncthreads();

    if (warp < 4) {
        float m = -3e38f;
        for (int h = lane; h < HH; h += 32) m = fmaxf(m, at_s[h][warp]);
#pragma unroll
        for (int o = 16; o; o >>= 1) m = fmaxf(m, __shfl_xor_sync(0xffffffffu, m, o));
        float s = 0.f;
        for (int h = lane; h < HH; h += 32) {
            float e = __expf(at_s[h][warp] - m);
            at_s[h][warp] = e;
            s += e;
        }
#pragma unroll
        for (int o = 16; o; o >>= 1) s += __shfl_xor_sync(0xffffffffu, s, o);
        float r = 1.f / s;
        for (int h = lane; h < HH; h += 32) at_s[h][warp] *= r;
    }
    __syncthreads();

    if (tid < DD) {
        const float* lvd = log_vec + (size_t)b * HH * DD + tid;
        float o0 = 0.f, o1 = 0.f, o2 = 0.f, o3 = 0.f;
#pragma unroll 4
        for (int h = 0; h < HH; h += 2) {
            float v0 = lvd[h * DD];
            float v1 = lvd[(h + 1) * DD];
            float4 w0 = *reinterpret_cast<float4*>(&at_s[h][0]);
            float4 w1 = *reinterpret_cast<float4*>(&at_s[h + 1][0]);
            o0 = fmaf(w0.x, v0, o0);
            o1 = fmaf(w0.y, v0, o1);
            o2 = fmaf(w0.z, v0, o2);
            o3 = fmaf(w0.w, v0, o3);
            o0 = fmaf(w1.x, v1, o0);
            o1 = fmaf(w1.y, v1, o1);
            o2 = fmaf(w1.z, v1, o2);
            o3 = fmaf(w1.w, v1, o3);
        }
        int nbase = b * NN + ng * 4;
        out[(size_t)(nbase + 0) * DD + tid] = o0;
        out[(size_t)(nbase + 1) * DD + tid] = o1;
        out[(size_t)(nbase + 2) * DD + tid] = o2;
        out[(size_t)(nbase + 3) * DD + tid] = o3;
    }
}

// ---------------- launch ----------------
extern "C" void kernel_launch(void* const* d_in, const int* in_sizes, int n_in,
                              void* d_out, int out_size) {
    const float* log_vec  = (const float*)d_in[0];   // [64,100,400] f32
    const int*   log_mask = (const int*)d_in[1];     // [64,100] i32
    const float* news_vec = (const float*)d_in[2];   // [64,32,400] f32
    const float* W1       = (const float*)d_in[3];   // [200,800] f32
    const float* b1       = (const float*)d_in[4];   // [200] f32
    const float* W2       = (const float*)d_in[5];   // [1,200] f32
    const float* b2       = (const float*)d_in[6];   // [1] f32
    float* out = (float*)d_out;                      // [64,32,400] f32

    gemm_tc_kernel<<<dim3(4, 66), 256>>>(log_vec, news_vec, W1, b1);
    logits_kernel<<<dim3(HH / HT, BB), 640>>>(log_mask, W2, b2);
    out_kernel<<<dim3(NN / 4, BB), 512>>>(log_vec, out);
}